// round 5
// baseline (speedup 1.0000x reference)
#include <cuda_runtime.h>

#define IN_F   4096
#define OUT_F  4096
#define RANK   8
#define TOK_PER_BLK 16

// ---- packed f32x2 helpers (ptxas never auto-fuses; PTX-only path) ----------
__device__ __forceinline__ unsigned long long fma2(unsigned long long a,
                                                   unsigned long long b,
                                                   unsigned long long c) {
    unsigned long long d;
    asm("fma.rn.f32x2 %0, %1, %2, %3;" : "=l"(d) : "l"(a), "l"(b), "l"(c));
    return d;
}
__device__ __forceinline__ float2 unpack2(unsigned long long v) {
    float2 f;
    asm("mov.b64 {%0, %1}, %2;" : "=f"(f.x), "=f"(f.y) : "l"(v));
    return f;
}
__device__ __forceinline__ unsigned long long pack2(float a, float b) {
    unsigned long long v;
    asm("mov.b64 %0, {%1, %2};" : "=l"(v) : "f"(a), "f"(b));
    return v;
}

// ---------------------------------------------------------------------------
// Fused TT-linear: one block owns 16 tokens end-to-end.
//   Phase A: t[16][8] = x_tile @ c1^T     (read-dominated)
//   Phase B: y_tile   = t @ c0^T + bias   (write-dominated)
// No global intermediate; blocks in different phases overlap HBM read and
// write streams. All inner products use packed fma.rn.f32x2.
// ---------------------------------------------------------------------------
__global__ void __launch_bounds__(256) tt_fused(const float* __restrict__ x,
                                                const float* __restrict__ c0,
                                                const float* __restrict__ c1,
                                                const float* __restrict__ bias,
                                                float* __restrict__ y) {
    __shared__ unsigned long long ts[TOK_PER_BLK][RANK];  // (t,t) pairs, 1 KB

    const int tid  = threadIdx.x;
    const int warp = tid >> 5;
    const int lane = tid & 31;
    const int token0 = blockIdx.x * TOK_PER_BLK;

    // ---------------- Phase A: 8 warps x 2 tokens, full IN_F row -----------
    {
        const int tokA = token0 + warp * 2;
        const ulonglong2* xp = reinterpret_cast<const ulonglong2*>(x)
                             + (size_t)tokA * (IN_F / 4);
        const ulonglong2* cp = reinterpret_cast<const ulonglong2*>(c1);

        unsigned long long acc[2][RANK];
#pragma unroll
        for (int t = 0; t < 2; t++)
#pragma unroll
            for (int r = 0; r < RANK; r++) acc[t][r] = 0ull;

#pragma unroll 2
        for (int i = lane; i < IN_F / 4; i += 32) {
            const ulonglong2 x0 = __ldcs(xp + i);                   // stream
            const ulonglong2 x1 = __ldcs(xp + (IN_F / 4) + i);
#pragma unroll
            for (int r = 0; r < RANK; r++) {
                const ulonglong2 c = __ldg(cp + (size_t)r * (IN_F / 4) + i);
                acc[0][r] = fma2(x0.x, c.x, acc[0][r]);
                acc[0][r] = fma2(x0.y, c.y, acc[0][r]);
                acc[1][r] = fma2(x1.x, c.x, acc[1][r]);
                acc[1][r] = fma2(x1.y, c.y, acc[1][r]);
            }
        }

#pragma unroll
        for (int t = 0; t < 2; t++)
#pragma unroll
            for (int r = 0; r < RANK; r++) {
                const float2 f = unpack2(acc[t][r]);
                float v = f.x + f.y;
#pragma unroll
                for (int off = 16; off; off >>= 1)
                    v += __shfl_xor_sync(0xffffffffu, v, off);
                if (lane == 0)
                    ts[warp * 2 + t][r] = pack2(v, v);
            }
    }
    __syncthreads();

    // ---------------- Phase B: 4 passes x 1024 outputs ----------------------
#pragma unroll
    for (int p = 0; p < 4; p++) {
        const int o = p * 1024 + tid * 4;          // 4 consecutive outputs

        float4 ca[4], cb[4];
#pragma unroll
        for (int j = 0; j < 4; j++) {
            const float4* c = reinterpret_cast<const float4*>(c0 + (size_t)(o + j) * RANK);
            ca[j] = __ldg(c);
            cb[j] = __ldg(c + 1);
        }
        unsigned long long cp01[RANK], cp23[RANK];
        cp01[0] = pack2(ca[0].x, ca[1].x);  cp23[0] = pack2(ca[2].x, ca[3].x);
        cp01[1] = pack2(ca[0].y, ca[1].y);  cp23[1] = pack2(ca[2].y, ca[3].y);
        cp01[2] = pack2(ca[0].z, ca[1].z);  cp23[2] = pack2(ca[2].z, ca[3].z);
        cp01[3] = pack2(ca[0].w, ca[1].w);  cp23[3] = pack2(ca[2].w, ca[3].w);
        cp01[4] = pack2(cb[0].x, cb[1].x);  cp23[4] = pack2(cb[2].x, cb[3].x);
        cp01[5] = pack2(cb[0].y, cb[1].y);  cp23[5] = pack2(cb[2].y, cb[3].y);
        cp01[6] = pack2(cb[0].z, cb[1].z);  cp23[6] = pack2(cb[2].z, cb[3].z);
        cp01[7] = pack2(cb[0].w, cb[1].w);  cp23[7] = pack2(cb[2].w, cb[3].w);

        const float4 bv = __ldg(reinterpret_cast<const float4*>(bias + o));
        const unsigned long long b01 = pack2(bv.x, bv.y);
        const unsigned long long b23 = pack2(bv.z, bv.w);

#pragma unroll 4
        for (int tok = 0; tok < TOK_PER_BLK; tok++) {
            const unsigned long long* tr = ts[tok];
            unsigned long long r01 = b01, r23 = b23;
#pragma unroll
            for (int r = 0; r < RANK; r++) {
                const unsigned long long tv = tr[r];
                r01 = fma2(cp01[r], tv, r01);
                r23 = fma2(cp23[r], tv, r23);
            }
            const float2 f01 = unpack2(r01);
            const float2 f23 = unpack2(r23);
            const float4 res = make_float4(f01.x, f01.y, f23.x, f23.y);
            __stcs(reinterpret_cast<float4*>(y + (size_t)(token0 + tok) * OUT_F + o),
                   res);
        }
    }
}

extern "C" void kernel_launch(void* const* d_in, const int* in_sizes, int n_in,
                              void* d_out, int out_size) {
    const float* x    = (const float*)d_in[0];   // [TOKENS, IN_F]
    const float* c0   = (const float*)d_in[1];   // [OUT_F, RANK]
    const float* c1   = (const float*)d_in[2];   // [RANK, IN_F]
    const float* bias = (const float*)d_in[3];   // [OUT_F]
    float* y = (float*)d_out;

    const int tokens = in_sizes[0] / IN_F;       // 8192

    tt_fused<<<tokens / TOK_PER_BLK, 256>>>(x, c0, c1, bias, y);
}

// round 6
// speedup vs baseline: 1.2833x; 1.2833x over previous
#include <cuda_runtime.h>

#define IN_F   4096
#define OUT_F  4096
#define RANK   8
#define MAX_TOKENS 8192

// Intermediate t[tok][r] = x @ core1^T  (256 KB, lives in L2)
__device__ float g_t[MAX_TOKENS * RANK];

// ---------------------------------------------------------------------------
// Stage 1: t[tok, r] = sum_i x[tok, i] * core1[r, i]
// Block = 128 threads = 4 warps, ALL covering the same 4 tokens; warp w
// reduces i-quarter [w*1024, (w+1)*1024). 8 lane-iterations per warp.
// 2048 blocks / 8192 warps, ~70 regs -> ~7 blocks/SM (~44% occ, 2x round 2).
// 4-token register reuse keeps c1 L1 traffic at 256 MB; x streams (__ldcs).
// ---------------------------------------------------------------------------
__global__ void __launch_bounds__(128) tt_stage1(const float* __restrict__ x,
                                                 const float* __restrict__ c1) {
    __shared__ float part[4][4][RANK];            // [warp][tok][r]

    const int warp = threadIdx.x >> 5;
    const int lane = threadIdx.x & 31;
    const int token0 = blockIdx.x * 4;

    // warp's i-quarter: 256 float4 starting at warp*256
    const float4* xp = reinterpret_cast<const float4*>(x)
                     + (size_t)token0 * (IN_F / 4) + warp * 256;
    const float4* cp = reinterpret_cast<const float4*>(c1) + warp * 256;

    float acc[4][RANK];
#pragma unroll
    for (int t = 0; t < 4; t++)
#pragma unroll
        for (int r = 0; r < RANK; r++) acc[t][r] = 0.0f;

    // 256 float4 per warp-quarter, 32 lanes -> 8 iterations
#pragma unroll 2
    for (int i = lane; i < 256; i += 32) {
        float4 xv[4];
#pragma unroll
        for (int t = 0; t < 4; t++)
            xv[t] = __ldcs(xp + (size_t)t * (IN_F / 4) + i);   // stream x
#pragma unroll
        for (int r = 0; r < RANK; r++) {
            const float4 c = __ldg(cp + (size_t)r * (IN_F / 4) + i);
#pragma unroll
            for (int t = 0; t < 4; t++) {
                acc[t][r] += xv[t].x * c.x + xv[t].y * c.y
                           + xv[t].z * c.z + xv[t].w * c.w;
            }
        }
    }

    // Warp tree-reduce the 32 accumulators, lane 0 deposits partials
#pragma unroll
    for (int t = 0; t < 4; t++)
#pragma unroll
        for (int r = 0; r < RANK; r++) {
            float v = acc[t][r];
#pragma unroll
            for (int off = 16; off; off >>= 1)
                v += __shfl_xor_sync(0xffffffffu, v, off);
            if (lane == 0) part[warp][t][r] = v;
        }
    __syncthreads();

    // 32 threads combine the 4 quarter-partials -> g_t
    if (threadIdx.x < 4 * RANK) {
        const int t = threadIdx.x >> 3;
        const int r = threadIdx.x & 7;
        g_t[(size_t)(token0 + t) * RANK + r] =
            part[0][t][r] + part[1][t][r] + part[2][t][r] + part[3][t][r];
    }
}

// ---------------------------------------------------------------------------
// Stage 2: y[tok, o] = bias[o] + sum_r t[tok, r] * core0[o, r]
// Block = 256 threads, 64 tokens x 1024 outputs. Each thread owns 4
// consecutive outputs (core0 coeffs in 32 regs, loaded once per 64 tokens:
// c0 L2 traffic halved vs round 2). t broadcast from 2 KB smem; stores are
// STG.128 (512B/warp contiguous) with evict-first (__stcs) for streaming y.
// Grid = 4 x 128 = 512 blocks, ~56 regs -> 4 blocks/SM (~50% occ).
// ---------------------------------------------------------------------------
__global__ void __launch_bounds__(256) tt_stage2(const float* __restrict__ c0,
                                                 const float* __restrict__ bias,
                                                 float* __restrict__ y) {
    __shared__ float ts[64 * RANK];               // t for 64 tokens (2 KB)
    const int tid = threadIdx.x;
    const int token0 = blockIdx.y * 64;
    const int o = blockIdx.x * 1024 + tid * 4;    // 4 consecutive outputs

    ts[tid]       = g_t[(size_t)token0 * RANK + tid];
    ts[tid + 256] = g_t[(size_t)token0 * RANK + tid + 256];

    float4 ca[4], cb[4];
#pragma unroll
    for (int j = 0; j < 4; j++) {
        const float4* c = reinterpret_cast<const float4*>(c0 + (size_t)(o + j) * RANK);
        ca[j] = __ldg(c);
        cb[j] = __ldg(c + 1);
    }
    const float4 bv = __ldg(reinterpret_cast<const float4*>(bias + o));

    __syncthreads();

#pragma unroll 4
    for (int tok = 0; tok < 64; tok++) {
        const float* tr = &ts[tok * RANK];
        const float t0 = tr[0], t1 = tr[1], t2 = tr[2], t3 = tr[3];
        const float t4 = tr[4], t5 = tr[5], t6 = tr[6], t7 = tr[7];

        float4 res;
        res.x = bv.x + ca[0].x * t0 + ca[0].y * t1 + ca[0].z * t2 + ca[0].w * t3
                     + cb[0].x * t4 + cb[0].y * t5 + cb[0].z * t6 + cb[0].w * t7;
        res.y = bv.y + ca[1].x * t0 + ca[1].y * t1 + ca[1].z * t2 + ca[1].w * t3
                     + cb[1].x * t4 + cb[1].y * t5 + cb[1].z * t6 + cb[1].w * t7;
        res.z = bv.z + ca[2].x * t0 + ca[2].y * t1 + ca[2].z * t2 + ca[2].w * t3
                     + cb[2].x * t4 + cb[2].y * t5 + cb[2].z * t6 + cb[2].w * t7;
        res.w = bv.w + ca[3].x * t0 + ca[3].y * t1 + ca[3].z * t2 + ca[3].w * t3
                     + cb[3].x * t4 + cb[3].y * t5 + cb[3].z * t6 + cb[3].w * t7;

        __stcs(reinterpret_cast<float4*>(y + (size_t)(token0 + tok) * OUT_F + o),
               res);
    }
}

extern "C" void kernel_launch(void* const* d_in, const int* in_sizes, int n_in,
                              void* d_out, int out_size) {
    const float* x    = (const float*)d_in[0];   // [TOKENS, IN_F]
    const float* c0   = (const float*)d_in[1];   // [OUT_F, RANK]
    const float* c1   = (const float*)d_in[2];   // [RANK, IN_F]
    const float* bias = (const float*)d_in[3];   // [OUT_F]
    float* y = (float*)d_out;

    const int tokens = in_sizes[0] / IN_F;       // 8192

    // Stage 1: 4 tokens/block, 4 warps share them (quarter-row each)
    tt_stage1<<<tokens / 4, 128>>>(x, c1);

    // Stage 2: 4 output chunks x 64-token groups = 512 blocks
    dim3 g2(OUT_F / 1024, tokens / 64);
    tt_stage2<<<g2, 256>>>(c0, bias, y);
}